// round 5
// baseline (speedup 1.0000x reference)
#include <cuda_runtime.h>
#include <cstdint>

#define NTOK 16384
#define DIN  1024
#define DH   256
#define DOUT 1024
#define NEXP 8

// scratch (static device globals; no allocation at runtime)
__device__ int   g_count[NEXP];
__device__ int   g_tok[NEXP * NTOK];
__device__ float g_wt[NEXP * NTOK];
__device__ float g_H[(size_t)NEXP * NTOK * DH];   // 128 MiB

// ---------------------------------------------------------------------------
// Kernel 0: zero the accumulated output region + expert counters
// ---------------------------------------------------------------------------
__global__ void moe_zero_kernel(float4* __restrict__ out4, int n4) {
    int i = blockIdx.x * blockDim.x + threadIdx.x;
    if (i < NEXP) g_count[i] = 0;
    float4 z = make_float4(0.f, 0.f, 0.f, 0.f);
    for (int idx = i; idx < n4; idx += gridDim.x * blockDim.x) out4[idx] = z;
}

// ---------------------------------------------------------------------------
// Kernel 1: gating. One warp per token: 8 fp32 dot products (exact), top-2,
// softmax, scatter into per-expert lists.
// ---------------------------------------------------------------------------
__global__ void moe_gate_kernel(const float* __restrict__ x,
                                const float* __restrict__ Wg,
                                const float* __restrict__ bg,
                                float* __restrict__ gate_out,  // [N, 8]
                                int N) {
    int warp = (blockIdx.x * blockDim.x + threadIdx.x) >> 5;
    int lane = threadIdx.x & 31;
    if (warp >= N) return;

    const float* xr = x + (size_t)warp * DIN;
    float acc[8];
#pragma unroll
    for (int e = 0; e < 8; e++) acc[e] = 0.f;

    for (int k = lane; k < DIN; k += 32) {
        float xv = xr[k];
        const float4* wrow = (const float4*)(Wg + (size_t)k * 8);
        float4 w0 = wrow[0];
        float4 w1 = wrow[1];
        acc[0] += xv * w0.x; acc[1] += xv * w0.y;
        acc[2] += xv * w0.z; acc[3] += xv * w0.w;
        acc[4] += xv * w1.x; acc[5] += xv * w1.y;
        acc[6] += xv * w1.z; acc[7] += xv * w1.w;
    }
#pragma unroll
    for (int off = 16; off; off >>= 1) {
#pragma unroll
        for (int e = 0; e < 8; e++)
            acc[e] += __shfl_xor_sync(0xFFFFFFFFu, acc[e], off);
    }

    if (lane == 0) {
        float lg[8];
#pragma unroll
        for (int e = 0; e < 8; e++) {
            lg[e] = acc[e] + bg[e];
            gate_out[(size_t)warp * 8 + e] = lg[e];
        }
        int i0 = 0; float m0 = lg[0];
#pragma unroll
        for (int e = 1; e < 8; e++) if (lg[e] > m0) { m0 = lg[e]; i0 = e; }
        int i1 = -1; float m1 = -1e30f;
#pragma unroll
        for (int e = 0; e < 8; e++) if (e != i0 && lg[e] > m1) { m1 = lg[e]; i1 = e; }
        float e1 = __expf(m1 - m0);
        float inv = 1.f / (1.f + e1);
        float w0 = inv;
        float w1 = e1 * inv;

        int p0 = atomicAdd(&g_count[i0], 1);
        g_tok[i0 * NTOK + p0] = warp;
        g_wt[i0 * NTOK + p0] = w0;
        int p1 = atomicAdd(&g_count[i1], 1);
        g_tok[i1 * NTOK + p1] = warp;
        g_wt[i1 * NTOK + p1] = w1;
    }
}

// ---------------------------------------------------------------------------
// TF32 mma helpers
// ---------------------------------------------------------------------------
__device__ __forceinline__ uint32_t f32_to_tf32(float f) {
    uint32_t r;
    asm("cvt.rna.tf32.f32 %0, %1;" : "=r"(r) : "f"(f));
    return r;
}

__device__ __forceinline__ void mma_tf32(float* c, const uint32_t* a, const uint32_t* b) {
    asm volatile(
        "mma.sync.aligned.m16n8k8.row.col.f32.tf32.tf32.f32 "
        "{%0,%1,%2,%3}, {%4,%5,%6,%7}, {%8,%9}, {%0,%1,%2,%3};\n"
        : "+f"(c[0]), "+f"(c[1]), "+f"(c[2]), "+f"(c[3])
        : "r"(a[0]), "r"(a[1]), "r"(a[2]), "r"(a[3]), "r"(b[0]), "r"(b[1]));
}

// Tiling: block 128x64, 8 warps (4 m x 2 n), warp tile 32x32 (2x4 atoms), BK=32
#define BM 128
#define BN 64
#define BK 32
#define A_STRIDE 36   // 36 % 32 == 4 -> conflict-free frag loads
#define B_STRIDE 72   // 72 % 32 == 8 -> conflict-free frag loads

// ---------------------------------------------------------------------------
// Kernel 2: H = relu(X[gathered] @ W1[e] + b1[e])   K=1024, Ncols=256
// ---------------------------------------------------------------------------
__global__ void __launch_bounds__(256, 2)
moe_gemm1_kernel(const float* __restrict__ x,
                 const float* __restrict__ W1,
                 const float* __restrict__ b1) {
    int e  = blockIdx.z;
    int m0 = blockIdx.y * BM;
    int n0 = blockIdx.x * BN;
    int M  = g_count[e];
    if (m0 >= M) return;

    __shared__ uint32_t As[BM][A_STRIDE];
    __shared__ uint32_t Bs[BK][B_STRIDE];

    int tid  = threadIdx.x;
    int wid  = tid >> 5;
    int lane = tid & 31;
    int wm   = wid & 3;          // 0..3 (m)
    int wn   = wid >> 2;         // 0..1 (n)
    int g    = lane >> 2;        // 0..7
    int t    = lane & 3;         // 0..3

    // A staging: row r = tid>>1, 16 floats at col (tid&1)*16
    int ar = tid >> 1;
    int ac = (tid & 1) * 16;
    int gm = m0 + ar;
    bool aval = (gm < M);
    const float* arow = x + (size_t)(aval ? g_tok[e * NTOK + gm] : 0) * DIN + ac;

    // B staging: row rb = tid>>3 (k), 8 floats at col (tid&7)*8
    int brk = tid >> 3;
    int bc  = (tid & 7) * 8;
    const float* bbase = W1 + (size_t)e * DIN * DH + n0 + bc;

    float acc[2][4][4];
#pragma unroll
    for (int i = 0; i < 2; i++)
#pragma unroll
        for (int j = 0; j < 4; j++)
#pragma unroll
            for (int q = 0; q < 4; q++) acc[i][j][q] = 0.f;

    float4 av[4], bv[2];
    // preload chunk 0
#pragma unroll
    for (int q = 0; q < 4; q++)
        av[q] = aval ? *(const float4*)(arow + q * 4) : make_float4(0.f, 0.f, 0.f, 0.f);
    bv[0] = *(const float4*)(bbase + (size_t)brk * DH);
    bv[1] = *(const float4*)(bbase + (size_t)brk * DH + 4);

    const int NK = DIN / BK;     // 32
    for (int kc = 0; kc < NK; kc++) {
        // store staged regs to smem (cvt to tf32)
#pragma unroll
        for (int q = 0; q < 4; q++) {
            As[ar][ac + q * 4 + 0] = f32_to_tf32(av[q].x);
            As[ar][ac + q * 4 + 1] = f32_to_tf32(av[q].y);
            As[ar][ac + q * 4 + 2] = f32_to_tf32(av[q].z);
            As[ar][ac + q * 4 + 3] = f32_to_tf32(av[q].w);
        }
        Bs[brk][bc + 0] = f32_to_tf32(bv[0].x);
        Bs[brk][bc + 1] = f32_to_tf32(bv[0].y);
        Bs[brk][bc + 2] = f32_to_tf32(bv[0].z);
        Bs[brk][bc + 3] = f32_to_tf32(bv[0].w);
        Bs[brk][bc + 4] = f32_to_tf32(bv[1].x);
        Bs[brk][bc + 5] = f32_to_tf32(bv[1].y);
        Bs[brk][bc + 6] = f32_to_tf32(bv[1].z);
        Bs[brk][bc + 7] = f32_to_tf32(bv[1].w);
        __syncthreads();

        // prefetch next chunk
        if (kc + 1 < NK) {
            int k0 = (kc + 1) * BK;
#pragma unroll
            for (int q = 0; q < 4; q++)
                av[q] = aval ? *(const float4*)(arow + k0 + q * 4)
                             : make_float4(0.f, 0.f, 0.f, 0.f);
            bv[0] = *(const float4*)(bbase + (size_t)(k0 + brk) * DH);
            bv[1] = *(const float4*)(bbase + (size_t)(k0 + brk) * DH + 4);
        }

        // compute 4 k-steps
#pragma unroll
        for (int kk = 0; kk < 4; kk++) {
            int kb = kk * 8;
            uint32_t af[2][4], bf[4][2];
#pragma unroll
            for (int i = 0; i < 2; i++) {
                int rb = wm * 32 + i * 16;
                af[i][0] = As[rb + g][kb + t];
                af[i][1] = As[rb + g + 8][kb + t];
                af[i][2] = As[rb + g][kb + t + 4];
                af[i][3] = As[rb + g + 8][kb + t + 4];
            }
#pragma unroll
            for (int j = 0; j < 4; j++) {
                int cb = wn * 32 + j * 8;
                bf[j][0] = Bs[kb + t][cb + g];
                bf[j][1] = Bs[kb + t + 4][cb + g];
            }
#pragma unroll
            for (int i = 0; i < 2; i++)
#pragma unroll
                for (int j = 0; j < 4; j++)
                    mma_tf32(acc[i][j], af[i], bf[j]);
        }
        __syncthreads();
    }

    // epilogue: relu(acc + bias) -> g_H
#pragma unroll
    for (int i = 0; i < 2; i++) {
        int row0 = m0 + wm * 32 + i * 16 + g;
        int row1 = row0 + 8;
#pragma unroll
        for (int j = 0; j < 4; j++) {
            int col = n0 + wn * 32 + j * 8 + 2 * t;
            float bx = b1[(size_t)e * DH + col];
            float by = b1[(size_t)e * DH + col + 1];
            if (row0 < M) {
                float2 h0;
                h0.x = fmaxf(acc[i][j][0] + bx, 0.f);
                h0.y = fmaxf(acc[i][j][1] + by, 0.f);
                *(float2*)(g_H + ((size_t)e * NTOK + row0) * DH + col) = h0;
            }
            if (row1 < M) {
                float2 h1;
                h1.x = fmaxf(acc[i][j][2] + bx, 0.f);
                h1.y = fmaxf(acc[i][j][3] + by, 0.f);
                *(float2*)(g_H + ((size_t)e * NTOK + row1) * DH + col) = h1;
            }
        }
    }
}

// ---------------------------------------------------------------------------
// Kernel 3: Y = H @ W2[e] + b2[e]; out[tok] += w * Y   K=256, Ncols=1024
// ---------------------------------------------------------------------------
__global__ void __launch_bounds__(256, 2)
moe_gemm2_kernel(const float* __restrict__ W2,
                 const float* __restrict__ b2,
                 float* __restrict__ out) {
    int e  = blockIdx.z;
    int m0 = blockIdx.y * BM;
    int n0 = blockIdx.x * BN;
    int M  = g_count[e];
    if (m0 >= M) return;

    __shared__ uint32_t As[BM][A_STRIDE];
    __shared__ uint32_t Bs[BK][B_STRIDE];

    int tid  = threadIdx.x;
    int wid  = tid >> 5;
    int lane = tid & 31;
    int wm   = wid & 3;
    int wn   = wid >> 2;
    int g    = lane >> 2;
    int t    = lane & 3;

    int ar = tid >> 1;
    int ac = (tid & 1) * 16;
    const float* arow = g_H + ((size_t)e * NTOK + (m0 + ar)) * DH + ac;

    int brk = tid >> 3;
    int bc  = (tid & 7) * 8;
    const float* bbase = W2 + (size_t)e * DH * DOUT + n0 + bc;

    float acc[2][4][4];
#pragma unroll
    for (int i = 0; i < 2; i++)
#pragma unroll
        for (int j = 0; j < 4; j++)
#pragma unroll
            for (int q = 0; q < 4; q++) acc[i][j][q] = 0.f;

    bool aval = (m0 + ar < M);   // guard against reading stale garbage
    float4 av[4], bv[2];
#pragma unroll
    for (int q = 0; q < 4; q++)
        av[q] = aval ? *(const float4*)(arow + q * 4) : make_float4(0.f, 0.f, 0.f, 0.f);
    bv[0] = *(const float4*)(bbase + (size_t)brk * DOUT);
    bv[1] = *(const float4*)(bbase + (size_t)brk * DOUT + 4);

    const int NK = DH / BK;      // 8
    for (int kc = 0; kc < NK; kc++) {
#pragma unroll
        for (int q = 0; q < 4; q++) {
            As[ar][ac + q * 4 + 0] = f32_to_tf32(av[q].x);
            As[ar][ac + q * 4 + 1] = f32_to_tf32(av[q].y);
            As[ar][ac + q * 4 + 2] = f32_to_tf32(av[q].z);
            As[ar][ac + q * 4 + 3] = f32_to_tf32(av[q].w);
        }
        Bs[brk][bc + 0] = f32_to_tf32(bv[0].x);
        Bs[brk][bc + 1] = f32_to_tf32(bv[0].y);
        Bs[brk][bc + 2] = f32_to_tf32(bv[0].z);
        Bs[brk][bc + 3] = f32_to_tf32(bv[0].w);
        Bs[brk][bc + 4] = f32_to_tf32(bv[1].x);
        Bs[brk][bc + 5] = f32_to_tf32(bv[1].y);
        Bs[brk][bc + 6] = f32_to_tf32(bv[1].z);
        Bs[brk][bc + 7] = f32_to_tf32(bv[1].w);
        __syncthreads();

        if (kc + 1 < NK) {
            int k0 = (kc + 1) * BK;
#pragma unroll
            for (int q = 0; q < 4; q++)
                av[q] = aval ? *(const float4*)(arow + k0 + q * 4)
                             : make_float4(0.f, 0.f, 0.f, 0.f);
            bv[0] = *(const float4*)(bbase + (size_t)(k0 + brk) * DOUT);
            bv[1] = *(const float4*)(bbase + (size_t)(k0 + brk) * DOUT + 4);
        }

#pragma unroll
        for (int kk = 0; kk < 4; kk++) {
            int kb = kk * 8;
            uint32_t af[2][4], bf[4][2];
#pragma unroll
            for (int i = 0; i < 2; i++) {
                int rb = wm * 32 + i * 16;
                af[i][0] = As[rb + g][kb + t];
                af[i][1] = As[rb + g + 8][kb + t];
                af[i][2] = As[rb + g][kb + t + 4];
                af[i][3] = As[rb + g + 8][kb + t + 4];
            }
#pragma unroll
            for (int j = 0; j < 4; j++) {
                int cb = wn * 32 + j * 8;
                bf[j][0] = Bs[kb + t][cb + g];
                bf[j][1] = Bs[kb + t + 4][cb + g];
            }
#pragma unroll
            for (int i = 0; i < 2; i++)
#pragma unroll
                for (int j = 0; j < 4; j++)
                    mma_tf32(acc[i][j], af[i], bf[j]);
        }
        __syncthreads();
    }

    // epilogue: out[tok] += w * (acc + bias)
#pragma unroll
    for (int i = 0; i < 2; i++) {
        int row0 = m0 + wm * 32 + i * 16 + g;
        int row1 = row0 + 8;
        int tok0 = 0, tok1 = 0;
        float w0 = 0.f, w1 = 0.f;
        if (row0 < M) { tok0 = g_tok[e * NTOK + row0]; w0 = g_wt[e * NTOK + row0]; }
        if (row1 < M) { tok1 = g_tok[e * NTOK + row1]; w1 = g_wt[e * NTOK + row1]; }
#pragma unroll
        for (int j = 0; j < 4; j++) {
            int col = n0 + wn * 32 + j * 8 + 2 * t;
            float bx = b2[(size_t)e * DOUT + col];
            float by = b2[(size_t)e * DOUT + col + 1];
            if (row0 < M) {
                float* o = out + (size_t)tok0 * DOUT + col;
                atomicAdd(o + 0, w0 * (acc[i][j][0] + bx));
                atomicAdd(o + 1, w0 * (acc[i][j][1] + by));
            }
            if (row1 < M) {
                float* o = out + (size_t)tok1 * DOUT + col;
                atomicAdd(o + 0, w1 * (acc[i][j][2] + bx));
                atomicAdd(o + 1, w1 * (acc[i][j][3] + by));
            }
        }
    }
}

// ---------------------------------------------------------------------------
// Launch
// ---------------------------------------------------------------------------
extern "C" void kernel_launch(void* const* d_in, const int* in_sizes, int n_in,
                              void* d_out, int out_size) {
    const float* x  = (const float*)d_in[0];
    const float* Wg = (const float*)d_in[1];
    const float* bg = (const float*)d_in[2];
    const float* W1 = (const float*)d_in[3];
    const float* b1 = (const float*)d_in[4];
    const float* W2 = (const float*)d_in[5];
    const float* b2 = (const float*)d_in[6];

    int N = in_sizes[0] / DIN;   // 16384
    float* out      = (float*)d_out;                    // [N, 1024]
    float* gate_out = (float*)d_out + (size_t)N * DOUT; // [N, 8]

    int n4 = (N * DOUT) / 4;
    moe_zero_kernel<<<2048, 256>>>((float4*)out, n4);

    int gate_blocks = (N * 32 + 255) / 256;
    moe_gate_kernel<<<gate_blocks, 256>>>(x, Wg, bg, gate_out, N);

    dim3 g1(DH / BN, (N + BM - 1) / BM, NEXP);     // 4 x 128 x 8
    moe_gemm1_kernel<<<g1, 256>>>(x, W1, b1);

    dim3 g2(DOUT / BN, (N + BM - 1) / BM, NEXP);   // 16 x 128 x 8
    moe_gemm2_kernel<<<g2, 256>>>(W2, b2, out);
}

// round 8
// speedup vs baseline: 1.0435x; 1.0435x over previous
#include <cuda_runtime.h>
#include <cstdint>

#define NTOK 16384
#define DIN  1024
#define DH   256
#define DOUT 1024
#define NEXP 8

// static device scratch (no runtime allocation)
__device__ int   g_count[NEXP];
__device__ int   g_tok[NEXP * NTOK];
__device__ float g_wt[NEXP * NTOK];
__device__ int   g_slot2[2 * NTOK];                 // per-token expert slots
__device__ float g_H[(size_t)NEXP * NTOK * DH];     // hidden activations
__device__ float g_Y[(size_t)NEXP * NTOK * DOUT];   // weighted expert outputs

// ---------------- helpers ----------------
__device__ __forceinline__ uint32_t f32_to_tf32(float f) {
    uint32_t r;
    asm("cvt.rna.tf32.f32 %0, %1;" : "=r"(r) : "f"(f));
    return r;
}

__device__ __forceinline__ void mma_tf32(float* c, const uint32_t* a, const uint32_t* b) {
    asm volatile(
        "mma.sync.aligned.m16n8k8.row.col.f32.tf32.tf32.f32 "
        "{%0,%1,%2,%3}, {%4,%5,%6,%7}, {%8,%9}, {%0,%1,%2,%3};\n"
        : "+f"(c[0]), "+f"(c[1]), "+f"(c[2]), "+f"(c[3])
        : "r"(a[0]), "r"(a[1]), "r"(a[2]), "r"(a[3]), "r"(b[0]), "r"(b[1]));
}

// Tiling: block tile 128x256, 8 warps (2m x 4n), warp tile 64x64, BK=16
#define BM 128
#define BN 256
#define BK 16
#define ASTR 20    // 20 mod 32 -> conflict-free scalar A frag loads (verified)
#define BSTR 264   // 264 mod 32 == 8 -> conflict-free B frag loads (same class as R4's 72)

// ---------------- kernel: zero expert counters ----------------
__global__ void zcnt_kernel() { if (threadIdx.x < NEXP) g_count[threadIdx.x] = 0; }

// ---------------- gate: exact fp32 logits, top-2, softmax, scatter ----------------
__global__ void moe_gate_kernel(const float* __restrict__ x, const float* __restrict__ Wg,
                                const float* __restrict__ bg, float* __restrict__ gate_out, int N) {
    int warp = (blockIdx.x * blockDim.x + threadIdx.x) >> 5;
    int lane = threadIdx.x & 31;
    if (warp >= N) return;
    const float* xr = x + (size_t)warp * DIN;
    float acc[8];
#pragma unroll
    for (int e = 0; e < 8; e++) acc[e] = 0.f;
    for (int k = lane; k < DIN; k += 32) {
        float xv = xr[k];
        const float4* wrow = (const float4*)(Wg + (size_t)k * 8);
        float4 w0 = wrow[0], w1 = wrow[1];
        acc[0] += xv * w0.x; acc[1] += xv * w0.y; acc[2] += xv * w0.z; acc[3] += xv * w0.w;
        acc[4] += xv * w1.x; acc[5] += xv * w1.y; acc[6] += xv * w1.z; acc[7] += xv * w1.w;
    }
#pragma unroll
    for (int off = 16; off; off >>= 1)
#pragma unroll
        for (int e = 0; e < 8; e++) acc[e] += __shfl_xor_sync(0xFFFFFFFFu, acc[e], off);
    if (lane == 0) {
        float lg[8];
#pragma unroll
        for (int e = 0; e < 8; e++) { lg[e] = acc[e] + bg[e]; gate_out[(size_t)warp * 8 + e] = lg[e]; }
        int i0 = 0; float m0 = lg[0];
#pragma unroll
        for (int e = 1; e < 8; e++) if (lg[e] > m0) { m0 = lg[e]; i0 = e; }
        int i1 = -1; float m1 = -1e30f;
#pragma unroll
        for (int e = 0; e < 8; e++) if (e != i0 && lg[e] > m1) { m1 = lg[e]; i1 = e; }
        float e1 = __expf(m1 - m0);
        float inv = 1.f / (1.f + e1);
        int p0 = atomicAdd(&g_count[i0], 1);
        g_tok[i0 * NTOK + p0] = warp; g_wt[i0 * NTOK + p0] = inv;
        g_slot2[2 * warp + 0] = i0 * NTOK + p0;
        int p1 = atomicAdd(&g_count[i1], 1);
        g_tok[i1 * NTOK + p1] = warp; g_wt[i1 * NTOK + p1] = e1 * inv;
        g_slot2[2 * warp + 1] = i1 * NTOK + p1;
    }
}

// ---------------- GEMM1: H = relu(X[gathered] @ W1 + b1), K=1024, Ncols=256 ------
__global__ void __launch_bounds__(256, 1)
moe_gemm1(const float* __restrict__ x, const float* __restrict__ W1,
          const float* __restrict__ b1) {
    int e = blockIdx.z, m0 = blockIdx.y * BM;
    int M = g_count[e];
    if (m0 >= M) return;

    __shared__ uint32_t As[BM][ASTR];
    __shared__ uint32_t Bs[BK][BSTR];

    int tid = threadIdx.x, wid = tid >> 5, lane = tid & 31;
    int wm = wid & 1, wn = wid >> 1;
    int g = lane >> 2, t = lane & 3;

    // A staging: row = tid>>1, 8 k-floats at (tid&1)*8
    int ar = tid >> 1, ac = (tid & 1) * 8;
    bool aval = (m0 + ar < M);
    const float* arow = x + (size_t)(aval ? g_tok[e * NTOK + m0 + ar] : 0) * DIN + ac;
    // B staging: k-row = tid>>4 (0..15), 16 n-floats at (tid&15)*16
    int brk = tid >> 4, bn = (tid & 15) * 16;
    const float* bbase = W1 + (size_t)e * DIN * DH + bn;

    float acc[4][8][4];
#pragma unroll
    for (int i = 0; i < 4; i++)
#pragma unroll
        for (int j = 0; j < 8; j++)
#pragma unroll
            for (int q = 0; q < 4; q++) acc[i][j][q] = 0.f;

    float4 av[2], bv[4];
    av[0] = aval ? *(const float4*)(arow + 0) : make_float4(0.f, 0.f, 0.f, 0.f);
    av[1] = aval ? *(const float4*)(arow + 4) : make_float4(0.f, 0.f, 0.f, 0.f);
#pragma unroll
    for (int q = 0; q < 4; q++)
        bv[q] = *(const float4*)(bbase + (size_t)brk * DH + q * 4);

    const int NK = DIN / BK;   // 64
    for (int kc = 0; kc < NK; kc++) {
        As[ar][ac + 0] = f32_to_tf32(av[0].x); As[ar][ac + 1] = f32_to_tf32(av[0].y);
        As[ar][ac + 2] = f32_to_tf32(av[0].z); As[ar][ac + 3] = f32_to_tf32(av[0].w);
        As[ar][ac + 4] = f32_to_tf32(av[1].x); As[ar][ac + 5] = f32_to_tf32(av[1].y);
        As[ar][ac + 6] = f32_to_tf32(av[1].z); As[ar][ac + 7] = f32_to_tf32(av[1].w);
#pragma unroll
        for (int q = 0; q < 4; q++) {
            Bs[brk][bn + q * 4 + 0] = f32_to_tf32(bv[q].x);
            Bs[brk][bn + q * 4 + 1] = f32_to_tf32(bv[q].y);
            Bs[brk][bn + q * 4 + 2] = f32_to_tf32(bv[q].z);
            Bs[brk][bn + q * 4 + 3] = f32_to_tf32(bv[q].w);
        }
        __syncthreads();

        if (kc + 1 < NK) {
            int k0 = (kc + 1) * BK;
            av[0] = aval ? *(const float4*)(arow + k0 + 0) : make_float4(0.f, 0.f, 0.f, 0.f);
            av[1] = aval ? *(const float4*)(arow + k0 + 4) : make_float4(0.f, 0.f, 0.f, 0.f);
#pragma unroll
            for (int q = 0; q < 4; q++)
                bv[q] = *(const float4*)(bbase + (size_t)(k0 + brk) * DH + q * 4);
        }

#pragma unroll
        for (int kk = 0; kk < 2; kk++) {
            int kb = kk * 8;
            uint32_t af[4][4], bf[8][2];
#pragma unroll
            for (int i = 0; i < 4; i++) {
                int rb = wm * 64 + i * 16;
                af[i][0] = As[rb + g][kb + t];
                af[i][1] = As[rb + g + 8][kb + t];
                af[i][2] = As[rb + g][kb + t + 4];
                af[i][3] = As[rb + g + 8][kb + t + 4];
            }
#pragma unroll
            for (int j = 0; j < 8; j++) {
                int cb = wn * 64 + j * 8;
                bf[j][0] = Bs[kb + t][cb + g];
                bf[j][1] = Bs[kb + t + 4][cb + g];
            }
#pragma unroll
            for (int i = 0; i < 4; i++)
#pragma unroll
                for (int j = 0; j < 8; j++)
                    mma_tf32(acc[i][j], af[i], bf[j]);
        }
        __syncthreads();
    }

    // epilogue: relu(acc + bias) -> g_H
#pragma unroll
    for (int i = 0; i < 4; i++) {
        int r0 = m0 + wm * 64 + i * 16 + g;
        int r1 = r0 + 8;
#pragma unroll
        for (int j = 0; j < 8; j++) {
            int col = wn * 64 + j * 8 + 2 * t;
            float bx = b1[(size_t)e * DH + col];
            float by = b1[(size_t)e * DH + col + 1];
            if (r0 < M) {
                float2 h0 = make_float2(fmaxf(acc[i][j][0] + bx, 0.f),
                                        fmaxf(acc[i][j][1] + by, 0.f));
                *(float2*)(g_H + ((size_t)e * NTOK + r0) * DH + col) = h0;
            }
            if (r1 < M) {
                float2 h1 = make_float2(fmaxf(acc[i][j][2] + bx, 0.f),
                                        fmaxf(acc[i][j][3] + by, 0.f));
                *(float2*)(g_H + ((size_t)e * NTOK + r1) * DH + col) = h1;
            }
        }
    }
}

// ---------------- GEMM2: g_Y[slot] = wt*(H @ W2 + b2), K=256, Ncols=1024 ----------
__global__ void __launch_bounds__(256, 1)
moe_gemm2(const float* __restrict__ W2, const float* __restrict__ b2) {
    int e = blockIdx.z, m0 = blockIdx.y * BM, n0 = blockIdx.x * BN;
    int M = g_count[e];
    if (m0 >= M) return;

    __shared__ uint32_t As[BM][ASTR];
    __shared__ uint32_t Bs[BK][BSTR];

    int tid = threadIdx.x, wid = tid >> 5, lane = tid & 31;
    int wm = wid & 1, wn = wid >> 1;
    int g = lane >> 2, t = lane & 3;

    int ar = tid >> 1, ac = (tid & 1) * 8;
    bool aval = (m0 + ar < M);
    const float* arow = g_H + ((size_t)e * NTOK + (m0 + ar)) * DH + ac;
    int brk = tid >> 4, bn = (tid & 15) * 16;
    const float* bbase = W2 + (size_t)e * DH * DOUT + n0 + bn;

    float acc[4][8][4];
#pragma unroll
    for (int i = 0; i < 4; i++)
#pragma unroll
        for (int j = 0; j < 8; j++)
#pragma unroll
            for (int q = 0; q < 4; q++) acc[i][j][q] = 0.f;

    float4 av[2], bv[4];
    av[0] = aval ? *(const float4*)(arow + 0) : make_float4(0.f, 0.f, 0.f, 0.f);
    av[1] = aval ? *(const float4*)(arow + 4) : make_float4(0.f, 0.f, 0.f, 0.f);
#pragma unroll
    for (int q = 0; q < 4; q++)
        bv[q] = *(const float4*)(bbase + (size_t)brk * DOUT + q * 4);

    const int NK = DH / BK;    // 16
    for (int kc = 0; kc < NK; kc++) {
        As[ar][ac + 0] = f32_to_tf32(av[0].x); As[ar][ac + 1] = f32_to_tf32(av[0].y);
        As[ar][ac + 2] = f32_to_tf32(av[0].z); As[ar][ac + 3] = f32_to_tf32(av[0].w);
        As[ar][ac + 4] = f32_to_tf32(av[1].x); As[ar][ac + 5] = f32_to_tf32(av[1].y);
        As[ar][ac + 6] = f32_to_tf32(av[1].z); As[ar][ac + 7] = f32_to_tf32(av[1].w);
#pragma unroll
        for (int q = 0; q < 4; q++) {
            Bs[brk][bn + q * 4 + 0] = f32_to_tf32(bv[q].x);
            Bs[brk][bn + q * 4 + 1] = f32_to_tf32(bv[q].y);
            Bs[brk][bn + q * 4 + 2] = f32_to_tf32(bv[q].z);
            Bs[brk][bn + q * 4 + 3] = f32_to_tf32(bv[q].w);
        }
        __syncthreads();

        if (kc + 1 < NK) {
            int k0 = (kc + 1) * BK;
            av[0] = aval ? *(const float4*)(arow + k0 + 0) : make_float4(0.f, 0.f, 0.f, 0.f);
            av[1] = aval ? *(const float4*)(arow + k0 + 4) : make_float4(0.f, 0.f, 0.f, 0.f);
#pragma unroll
            for (int q = 0; q < 4; q++)
                bv[q] = *(const float4*)(bbase + (size_t)(k0 + brk) * DOUT + q * 4);
        }

#pragma unroll
        for (int kk = 0; kk < 2; kk++) {
            int kb = kk * 8;
            uint32_t af[4][4], bf[8][2];
#pragma unroll
            for (int i = 0; i < 4; i++) {
                int rb = wm * 64 + i * 16;
                af[i][0] = As[rb + g][kb + t];
                af[i][1] = As[rb + g + 8][kb + t];
                af[i][2] = As[rb + g][kb + t + 4];
                af[i][3] = As[rb + g + 8][kb + t + 4];
            }
#pragma unroll
            for (int j = 0; j < 8; j++) {
                int cb = wn * 64 + j * 8;
                bf[j][0] = Bs[kb + t][cb + g];
                bf[j][1] = Bs[kb + t + 4][cb + g];
            }
#pragma unroll
            for (int i = 0; i < 4; i++)
#pragma unroll
                for (int j = 0; j < 8; j++)
                    mma_tf32(acc[i][j], af[i], bf[j]);
        }
        __syncthreads();
    }

    // epilogue: g_Y[slot] = wt * (acc + bias)   (plain stores, no atomics)
#pragma unroll
    for (int i = 0; i < 4; i++) {
        int r0 = m0 + wm * 64 + i * 16 + g;
        int r1 = r0 + 8;
        float w0 = (r0 < M) ? g_wt[e * NTOK + r0] : 0.f;
        float w1 = (r1 < M) ? g_wt[e * NTOK + r1] : 0.f;
#pragma unroll
        for (int j = 0; j < 8; j++) {
            int col = n0 + wn * 64 + j * 8 + 2 * t;
            float bx = b2[(size_t)e * DOUT + col];
            float by = b2[(size_t)e * DOUT + col + 1];
            if (r0 < M) {
                float2 v = make_float2(w0 * (acc[i][j][0] + bx), w0 * (acc[i][j][1] + by));
                *(float2*)(g_Y + ((size_t)e * NTOK + r0) * DOUT + col) = v;
            }
            if (r1 < M) {
                float2 v = make_float2(w1 * (acc[i][j][2] + bx), w1 * (acc[i][j][3] + by));
                *(float2*)(g_Y + ((size_t)e * NTOK + r1) * DOUT + col) = v;
            }
        }
    }
}

// ---------------- combine: out[tok] = Y[slotA] + Y[slotB] ----------------
__global__ void combine_kernel(float* __restrict__ out) {
    int tok = blockIdx.x, tid = threadIdx.x;
    int sa = g_slot2[2 * tok], sb = g_slot2[2 * tok + 1];
    float4 a = ((const float4*)(g_Y + (size_t)sa * DOUT))[tid];
    float4 b = ((const float4*)(g_Y + (size_t)sb * DOUT))[tid];
    ((float4*)(out + (size_t)tok * DOUT))[tid] =
        make_float4(a.x + b.x, a.y + b.y, a.z + b.z, a.w + b.w);
}

// ---------------- launch ----------------
extern "C" void kernel_launch(void* const* d_in, const int* in_sizes, int n_in,
                              void* d_out, int out_size) {
    const float* x  = (const float*)d_in[0];
    const float* Wg = (const float*)d_in[1];
    const float* bg = (const float*)d_in[2];
    const float* W1 = (const float*)d_in[3];
    const float* b1 = (const float*)d_in[4];
    const float* W2 = (const float*)d_in[5];
    const float* b2 = (const float*)d_in[6];

    int N = in_sizes[0] / DIN;   // 16384
    float* out      = (float*)d_out;
    float* gate_out = (float*)d_out + (size_t)N * DOUT;

    zcnt_kernel<<<1, 32>>>();
    moe_gate_kernel<<<(N * 32 + 255) / 256, 256>>>(x, Wg, bg, gate_out, N);

    dim3 g1(1, NTOK / BM, NEXP);          // 1 x 128 x 8
    moe_gemm1<<<g1, 256>>>(x, W1, b1);

    dim3 g2(DOUT / BN, NTOK / BM, NEXP);  // 4 x 128 x 8
    moe_gemm2<<<g2, 256>>>(W2, b2);

    combine_kernel<<<N, 256>>>(out);
}

// round 10
// speedup vs baseline: 1.5254x; 1.4619x over previous
#include <cuda_runtime.h>
#include <cuda_fp16.h>
#include <cstdint>

#define NTOK 16384
#define DIN  1024
#define DH   256
#define DOUT 1024
#define NEXP 8

// static device scratch (no runtime allocation)
__device__ int   g_count[NEXP];
__device__ int   g_tok[NEXP * NTOK];
__device__ float g_wt[NEXP * NTOK];
__device__ int   g_slot2[2 * NTOK];                 // per-token expert slots
__device__ float g_H[(size_t)NEXP * NTOK * DH];     // hidden activations (fp32)
__device__ float g_Y[(size_t)NEXP * NTOK * DOUT];   // weighted expert outputs

// ---------------- helpers ----------------
__device__ __forceinline__ uint32_t pkh2(float lo, float hi) {
    __half2 h = __floats2half2_rn(lo, hi);
    return *(uint32_t*)&h;
}

__device__ __forceinline__ void mma_f16(float* c, const uint32_t* a, const uint32_t* b) {
    asm volatile(
        "mma.sync.aligned.m16n8k16.row.col.f32.f16.f16.f32 "
        "{%0,%1,%2,%3}, {%4,%5,%6,%7}, {%8,%9}, {%0,%1,%2,%3};\n"
        : "+f"(c[0]), "+f"(c[1]), "+f"(c[2]), "+f"(c[3])
        : "r"(a[0]), "r"(a[1]), "r"(a[2]), "r"(a[3]), "r"(b[0]), "r"(b[1]));
}

// Tiling: block tile 128x256, 8 warps (2m x 4n), warp tile 64x64.
// Chunk = 32 k-halves = 16 b32 k-pair words (same word geometry as R8's BK=16 tf32).
#define BM 128
#define BN 256
#define BKW 16     // k-pair words per chunk
#define ASTR 20    // R8-proven conflict-free strides
#define BSTR 264

// ---------------- kernel: zero expert counters ----------------
__global__ void zcnt_kernel() { if (threadIdx.x < NEXP) g_count[threadIdx.x] = 0; }

// ---------------- gate: exact fp32 logits, top-2, softmax, scatter ----------------
__global__ void moe_gate_kernel(const float* __restrict__ x, const float* __restrict__ Wg,
                                const float* __restrict__ bg, float* __restrict__ gate_out, int N) {
    int warp = (blockIdx.x * blockDim.x + threadIdx.x) >> 5;
    int lane = threadIdx.x & 31;
    if (warp >= N) return;
    const float* xr = x + (size_t)warp * DIN;
    float acc[8];
#pragma unroll
    for (int e = 0; e < 8; e++) acc[e] = 0.f;
    for (int k = lane; k < DIN; k += 32) {
        float xv = xr[k];
        const float4* wrow = (const float4*)(Wg + (size_t)k * 8);
        float4 w0 = wrow[0], w1 = wrow[1];
        acc[0] += xv * w0.x; acc[1] += xv * w0.y; acc[2] += xv * w0.z; acc[3] += xv * w0.w;
        acc[4] += xv * w1.x; acc[5] += xv * w1.y; acc[6] += xv * w1.z; acc[7] += xv * w1.w;
    }
#pragma unroll
    for (int off = 16; off; off >>= 1)
#pragma unroll
        for (int e = 0; e < 8; e++) acc[e] += __shfl_xor_sync(0xFFFFFFFFu, acc[e], off);
    if (lane == 0) {
        float lg[8];
#pragma unroll
        for (int e = 0; e < 8; e++) { lg[e] = acc[e] + bg[e]; gate_out[(size_t)warp * 8 + e] = lg[e]; }
        int i0 = 0; float m0 = lg[0];
#pragma unroll
        for (int e = 1; e < 8; e++) if (lg[e] > m0) { m0 = lg[e]; i0 = e; }
        int i1 = -1; float m1 = -1e30f;
#pragma unroll
        for (int e = 0; e < 8; e++) if (e != i0 && lg[e] > m1) { m1 = lg[e]; i1 = e; }
        float e1 = __expf(m1 - m0);
        float inv = 1.f / (1.f + e1);
        int p0 = atomicAdd(&g_count[i0], 1);
        g_tok[i0 * NTOK + p0] = warp; g_wt[i0 * NTOK + p0] = inv;
        g_slot2[2 * warp + 0] = i0 * NTOK + p0;
        int p1 = atomicAdd(&g_count[i1], 1);
        g_tok[i1 * NTOK + p1] = warp; g_wt[i1 * NTOK + p1] = e1 * inv;
        g_slot2[2 * warp + 1] = i1 * NTOK + p1;
    }
}

// ---------------- GEMM1: H = relu(X[gathered] @ W1 + b1), K=1024, Ncols=256 ------
__global__ void __launch_bounds__(256, 1)
moe_gemm1(const float* __restrict__ x, const float* __restrict__ W1,
          const float* __restrict__ b1) {
    int e = blockIdx.z, m0 = blockIdx.y * BM;
    int M = g_count[e];
    if (m0 >= M) return;

    __shared__ uint32_t As[BM][ASTR];    // [m][k-pair word]
    __shared__ uint32_t Bs[BKW][BSTR];   // [k-pair word][n]

    int tid = threadIdx.x, wid = tid >> 5, lane = tid & 31;
    int wm = wid & 1, wn = wid >> 1;
    int g = lane >> 2, t = lane & 3;

    // A staging: row = tid>>1, 16 k-floats at (tid&1)*16 -> 8 packed words
    int ar = tid >> 1, acf = (tid & 1) * 16, acw = (tid & 1) * 8;
    bool aval = (m0 + ar < M);
    const float* arow = x + (size_t)(aval ? g_tok[e * NTOK + m0 + ar] : 0) * DIN + acf;
    // B staging: k-pair row kp = tid>>4 (0..15), 16 n-floats at (tid&15)*16,
    // loads gmem k-rows (2kp, 2kp+1) of the chunk
    int kp = tid >> 4, bn = (tid & 15) * 16;
    const float* b0p = W1 + (size_t)e * DIN * DH + (size_t)(2 * kp) * DH + bn;
    const float* b1p = b0p + DH;

    float acc[4][8][4];
#pragma unroll
    for (int i = 0; i < 4; i++)
#pragma unroll
        for (int j = 0; j < 8; j++)
#pragma unroll
            for (int q = 0; q < 4; q++) acc[i][j][q] = 0.f;

    float4 av[4], bv0[4], bv1[4];
#pragma unroll
    for (int q = 0; q < 4; q++)
        av[q] = aval ? *(const float4*)(arow + q * 4) : make_float4(0.f, 0.f, 0.f, 0.f);
#pragma unroll
    for (int q = 0; q < 4; q++) {
        bv0[q] = *(const float4*)(b0p + q * 4);
        bv1[q] = *(const float4*)(b1p + q * 4);
    }

    const int NK = DIN / 32;   // 32 chunks of 32 k
    for (int kc = 0; kc < NK; kc++) {
        // pack + store A (8 words = 2 uint4)
        {
            uint4 w0, w1;
            w0.x = pkh2(av[0].x, av[0].y); w0.y = pkh2(av[0].z, av[0].w);
            w0.z = pkh2(av[1].x, av[1].y); w0.w = pkh2(av[1].z, av[1].w);
            w1.x = pkh2(av[2].x, av[2].y); w1.y = pkh2(av[2].z, av[2].w);
            w1.z = pkh2(av[3].x, av[3].y); w1.w = pkh2(av[3].z, av[3].w);
            *(uint4*)&As[ar][acw + 0] = w0;
            *(uint4*)&As[ar][acw + 4] = w1;
        }
        // pack + store B (16 words = 4 uint4): word(kp, n) = {B[2kp][n], B[2kp+1][n]}
#pragma unroll
        for (int q = 0; q < 4; q++) {
            uint4 w;
            w.x = pkh2(bv0[q].x, bv1[q].x);
            w.y = pkh2(bv0[q].y, bv1[q].y);
            w.z = pkh2(bv0[q].z, bv1[q].z);
            w.w = pkh2(bv0[q].w, bv1[q].w);
            *(uint4*)&Bs[kp][bn + q * 4] = w;
        }
        __syncthreads();

        if (kc + 1 < NK) {
            int k0 = (kc + 1) * 32;
#pragma unroll
            for (int q = 0; q < 4; q++)
                av[q] = aval ? *(const float4*)(arow + k0 + q * 4)
                             : make_float4(0.f, 0.f, 0.f, 0.f);
            size_t bo = (size_t)k0 * DH;
#pragma unroll
            for (int q = 0; q < 4; q++) {
                bv0[q] = *(const float4*)(b0p + bo + q * 4);
                bv1[q] = *(const float4*)(b1p + bo + q * 4);
            }
        }

#pragma unroll
        for (int kk = 0; kk < 2; kk++) {
            int kb = kk * 8;
            uint32_t af[4][4], bf[8][2];
#pragma unroll
            for (int i = 0; i < 4; i++) {
                int rb = wm * 64 + i * 16;
                af[i][0] = As[rb + g][kb + t];
                af[i][1] = As[rb + g + 8][kb + t];
                af[i][2] = As[rb + g][kb + t + 4];
                af[i][3] = As[rb + g + 8][kb + t + 4];
            }
#pragma unroll
            for (int j = 0; j < 8; j++) {
                int cb = wn * 64 + j * 8;
                bf[j][0] = Bs[kb + t][cb + g];
                bf[j][1] = Bs[kb + t + 4][cb + g];
            }
#pragma unroll
            for (int i = 0; i < 4; i++)
#pragma unroll
                for (int j = 0; j < 8; j++)
                    mma_f16(acc[i][j], af[i], bf[j]);
        }
        __syncthreads();
    }

    // epilogue: relu(acc + bias) -> g_H  (unchanged from R8)
#pragma unroll
    for (int i = 0; i < 4; i++) {
        int r0 = m0 + wm * 64 + i * 16 + g;
        int r1 = r0 + 8;
#pragma unroll
        for (int j = 0; j < 8; j++) {
            int col = wn * 64 + j * 8 + 2 * t;
            float bx = b1[(size_t)e * DH + col];
            float by = b1[(size_t)e * DH + col + 1];
            if (r0 < M) {
                float2 h0 = make_float2(fmaxf(acc[i][j][0] + bx, 0.f),
                                        fmaxf(acc[i][j][1] + by, 0.f));
                *(float2*)(g_H + ((size_t)e * NTOK + r0) * DH + col) = h0;
            }
            if (r1 < M) {
                float2 h1 = make_float2(fmaxf(acc[i][j][2] + bx, 0.f),
                                        fmaxf(acc[i][j][3] + by, 0.f));
                *(float2*)(g_H + ((size_t)e * NTOK + r1) * DH + col) = h1;
            }
        }
    }
}

// ---------------- GEMM2: g_Y[slot] = wt*(H @ W2 + b2), K=256, Ncols=1024 ----------
__global__ void __launch_bounds__(256, 1)
moe_gemm2(const float* __restrict__ W2, const float* __restrict__ b2) {
    int e = blockIdx.z, m0 = blockIdx.y * BM, n0 = blockIdx.x * BN;
    int M = g_count[e];
    if (m0 >= M) return;

    __shared__ uint32_t As[BM][ASTR];
    __shared__ uint32_t Bs[BKW][BSTR];

    int tid = threadIdx.x, wid = tid >> 5, lane = tid & 31;
    int wm = wid & 1, wn = wid >> 1;
    int g = lane >> 2, t = lane & 3;

    int ar = tid >> 1, acf = (tid & 1) * 16, acw = (tid & 1) * 8;
    bool aval = (m0 + ar < M);
    const float* arow = g_H + ((size_t)e * NTOK + (m0 + ar)) * DH + acf;
    int kp = tid >> 4, bn = (tid & 15) * 16;
    const float* b0p = W2 + (size_t)e * DH * DOUT + (size_t)(2 * kp) * DOUT + n0 + bn;
    const float* b1p = b0p + DOUT;

    float acc[4][8][4];
#pragma unroll
    for (int i = 0; i < 4; i++)
#pragma unroll
        for (int j = 0; j < 8; j++)
#pragma unroll
            for (int q = 0; q < 4; q++) acc[i][j][q] = 0.f;

    float4 av[4], bv0[4], bv1[4];
#pragma unroll
    for (int q = 0; q < 4; q++)
        av[q] = aval ? *(const float4*)(arow + q * 4) : make_float4(0.f, 0.f, 0.f, 0.f);
#pragma unroll
    for (int q = 0; q < 4; q++) {
        bv0[q] = *(const float4*)(b0p + q * 4);
        bv1[q] = *(const float4*)(b1p + q * 4);
    }

    const int NK = DH / 32;    // 8 chunks
    for (int kc = 0; kc < NK; kc++) {
        {
            uint4 w0, w1;
            w0.x = pkh2(av[0].x, av[0].y); w0.y = pkh2(av[0].z, av[0].w);
            w0.z = pkh2(av[1].x, av[1].y); w0.w = pkh2(av[1].z, av[1].w);
            w1.x = pkh2(av[2].x, av[2].y); w1.y = pkh2(av[2].z, av[2].w);
            w1.z = pkh2(av[3].x, av[3].y); w1.w = pkh2(av[3].z, av[3].w);
            *(uint4*)&As[ar][acw + 0] = w0;
            *(uint4*)&As[ar][acw + 4] = w1;
        }
#pragma unroll
        for (int q = 0; q < 4; q++) {
            uint4 w;
            w.x = pkh2(bv0[q].x, bv1[q].x);
            w.y = pkh2(bv0[q].y, bv1[q].y);
            w.z = pkh2(bv0[q].z, bv1[q].z);
            w.w = pkh2(bv0[q].w, bv1[q].w);
            *(uint4*)&Bs[kp][bn + q * 4] = w;
        }
        __syncthreads();

        if (kc + 1 < NK) {
            int k0 = (kc + 1) * 32;
#pragma unroll
            for (int q = 0; q < 4; q++)
                av[q] = aval ? *(const float4*)(arow + k0 + q * 4)
                             : make_float4(0.f, 0.f, 0.f, 0.f);
            size_t bo = (size_t)k0 * DOUT;
#pragma unroll
            for (int q = 0; q < 4; q++) {
                bv0[q] = *(const float4*)(b0p + bo + q * 4);
                bv1[q] = *(const float4*)(b1p + bo + q * 4);
            }
        }

#pragma unroll
        for (int kk = 0; kk < 2; kk++) {
            int kb = kk * 8;
            uint32_t af[4][4], bf[8][2];
#pragma unroll
            for (int i = 0; i < 4; i++) {
                int rb = wm * 64 + i * 16;
                af[i][0] = As[rb + g][kb + t];
                af[i][1] = As[rb + g + 8][kb + t];
                af[i][2] = As[rb + g][kb + t + 4];
                af[i][3] = As[rb + g + 8][kb + t + 4];
            }
#pragma unroll
            for (int j = 0; j < 8; j++) {
                int cb = wn * 64 + j * 8;
                bf[j][0] = Bs[kb + t][cb + g];
                bf[j][1] = Bs[kb + t + 4][cb + g];
            }
#pragma unroll
            for (int i = 0; i < 4; i++)
#pragma unroll
                for (int j = 0; j < 8; j++)
                    mma_f16(acc[i][j], af[i], bf[j]);
        }
        __syncthreads();
    }

    // epilogue: g_Y[slot] = wt * (acc + bias)  (unchanged from R8)
#pragma unroll
    for (int i = 0; i < 4; i++) {
        int r0 = m0 + wm * 64 + i * 16 + g;
        int r1 = r0 + 8;
        float w0 = (r0 < M) ? g_wt[e * NTOK + r0] : 0.f;
        float w1 = (r1 < M) ? g_wt[e * NTOK + r1] : 0.f;
#pragma unroll
        for (int j = 0; j < 8; j++) {
            int col = n0 + wn * 64 + j * 8 + 2 * t;
            float bx = b2[(size_t)e * DOUT + col];
            float by = b2[(size_t)e * DOUT + col + 1];
            if (r0 < M) {
                float2 v = make_float2(w0 * (acc[i][j][0] + bx), w0 * (acc[i][j][1] + by));
                *(float2*)(g_Y + ((size_t)e * NTOK + r0) * DOUT + col) = v;
            }
            if (r1 < M) {
                float2 v = make_float2(w1 * (acc[i][j][2] + bx), w1 * (acc[i][j][3] + by));
                *(float2*)(g_Y + ((size_t)e * NTOK + r1) * DOUT + col) = v;
            }
        }
    }
}

// ---------------- combine: out[tok] = Y[slotA] + Y[slotB] ----------------
__global__ void combine_kernel(float* __restrict__ out) {
    int tok = blockIdx.x, tid = threadIdx.x;
    int sa = g_slot2[2 * tok], sb = g_slot2[2 * tok + 1];
    float4 a = ((const float4*)(g_Y + (size_t)sa * DOUT))[tid];
    float4 b = ((const float4*)(g_Y + (size_t)sb * DOUT))[tid];
    ((float4*)(out + (size_t)tok * DOUT))[tid] =
        make_float4(a.x + b.x, a.y + b.y, a.z + b.z, a.w + b.w);
}

// ---------------- launch ----------------
extern "C" void kernel_launch(void* const* d_in, const int* in_sizes, int n_in,
                              void* d_out, int out_size) {
    const float* x  = (const float*)d_in[0];
    const float* Wg = (const float*)d_in[1];
    const float* bg = (const float*)d_in[2];
    const float* W1 = (const float*)d_in[3];
    const float* b1 = (const float*)d_in[4];
    const float* W2 = (const float*)d_in[5];
    const float* b2 = (const float*)d_in[6];

    int N = in_sizes[0] / DIN;   // 16384
    float* out      = (float*)d_out;
    float* gate_out = (float*)d_out + (size_t)N * DOUT;

    zcnt_kernel<<<1, 32>>>();
    moe_gate_kernel<<<(N * 32 + 255) / 256, 256>>>(x, Wg, bg, gate_out, N);

    dim3 g1(1, NTOK / BM, NEXP);          // 1 x 128 x 8
    moe_gemm1<<<g1, 256>>>(x, W1, b1);

    dim3 g2(DOUT / BN, NTOK / BM, NEXP);  // 4 x 128 x 8
    moe_gemm2<<<g2, 256>>>(W2, b2);

    combine_kernel<<<N, 256>>>(out);
}

// round 11
// speedup vs baseline: 1.6744x; 1.0977x over previous
#include <cuda_runtime.h>
#include <cuda_fp16.h>
#include <cstdint>

#define NTOK 16384
#define DIN  1024
#define DH   256
#define DOUT 1024
#define NEXP 8

// static device scratch (no runtime allocation)
__device__ int   g_count[NEXP];
__device__ int   g_tok[NEXP * NTOK];
__device__ float g_wt[NEXP * NTOK];
__device__ int   g_slot2[2 * NTOK];                 // per-token expert slots
__device__ float g_H[(size_t)NEXP * NTOK * DH];     // hidden activations (fp32)
__device__ float g_Y[(size_t)NEXP * NTOK * DOUT];   // weighted expert outputs

// ---------------- helpers ----------------
__device__ __forceinline__ uint32_t pkh2(float lo, float hi) {
    __half2 h = __floats2half2_rn(lo, hi);
    return *(uint32_t*)&h;
}

__device__ __forceinline__ void mma_f16(float* c, const uint32_t* a, const uint32_t* b) {
    asm volatile(
        "mma.sync.aligned.m16n8k16.row.col.f32.f16.f16.f32 "
        "{%0,%1,%2,%3}, {%4,%5,%6,%7}, {%8,%9}, {%0,%1,%2,%3};\n"
        : "+f"(c[0]), "+f"(c[1]), "+f"(c[2]), "+f"(c[3])
        : "r"(a[0]), "r"(a[1]), "r"(a[2]), "r"(a[3]), "r"(b[0]), "r"(b[1]));
}

// Tiling: block tile 128x256, 8 warps (2m x 4n), warp tile 64x64.
// Chunk = 32 k-halves = 16 b32 k-pair words.
#define BM 128
#define BN 256
#define BKW 16     // k-pair words per chunk
#define ASTR 20
#define BSTR 264

// ---------------- kernel: zero expert counters ----------------
__global__ void zcnt_kernel() { if (threadIdx.x < NEXP) g_count[threadIdx.x] = 0; }

// ---------------- gate: exact fp32 logits, top-2, softmax, scatter ----------------
__global__ void moe_gate_kernel(const float* __restrict__ x, const float* __restrict__ Wg,
                                const float* __restrict__ bg, float* __restrict__ gate_out, int N) {
    int warp = (blockIdx.x * blockDim.x + threadIdx.x) >> 5;
    int lane = threadIdx.x & 31;
    if (warp >= N) return;
    const float* xr = x + (size_t)warp * DIN;
    float acc[8];
#pragma unroll
    for (int e = 0; e < 8; e++) acc[e] = 0.f;
    for (int k = lane; k < DIN; k += 32) {
        float xv = xr[k];
        const float4* wrow = (const float4*)(Wg + (size_t)k * 8);
        float4 w0 = wrow[0], w1 = wrow[1];
        acc[0] += xv * w0.x; acc[1] += xv * w0.y; acc[2] += xv * w0.z; acc[3] += xv * w0.w;
        acc[4] += xv * w1.x; acc[5] += xv * w1.y; acc[6] += xv * w1.z; acc[7] += xv * w1.w;
    }
#pragma unroll
    for (int off = 16; off; off >>= 1)
#pragma unroll
        for (int e = 0; e < 8; e++) acc[e] += __shfl_xor_sync(0xFFFFFFFFu, acc[e], off);
    if (lane == 0) {
        float lg[8];
#pragma unroll
        for (int e = 0; e < 8; e++) { lg[e] = acc[e] + bg[e]; gate_out[(size_t)warp * 8 + e] = lg[e]; }
        int i0 = 0; float m0 = lg[0];
#pragma unroll
        for (int e = 1; e < 8; e++) if (lg[e] > m0) { m0 = lg[e]; i0 = e; }
        int i1 = -1; float m1 = -1e30f;
#pragma unroll
        for (int e = 0; e < 8; e++) if (e != i0 && lg[e] > m1) { m1 = lg[e]; i1 = e; }
        float e1 = __expf(m1 - m0);
        float inv = 1.f / (1.f + e1);
        int p0 = atomicAdd(&g_count[i0], 1);
        g_tok[i0 * NTOK + p0] = warp; g_wt[i0 * NTOK + p0] = inv;
        g_slot2[2 * warp + 0] = i0 * NTOK + p0;
        int p1 = atomicAdd(&g_count[i1], 1);
        g_tok[i1 * NTOK + p1] = warp; g_wt[i1 * NTOK + p1] = e1 * inv;
        g_slot2[2 * warp + 1] = i1 * NTOK + p1;
    }
}

// ---------------- GEMM1: H = relu(X[gathered] @ W1 + b1), K=1024, Ncols=256 ------
__global__ void __launch_bounds__(256, 1)
moe_gemm1(const float* __restrict__ x, const float* __restrict__ W1,
          const float* __restrict__ b1) {
    int e = blockIdx.z, m0 = blockIdx.y * BM;
    int M = g_count[e];
    if (m0 >= M) return;

    __shared__ uint32_t As[BM][ASTR];    // [m][k-pair word]
    __shared__ uint32_t Bs[BKW][BSTR];   // [k-pair word][n]

    int tid = threadIdx.x, wid = tid >> 5, lane = tid & 31;
    int wm = wid & 1, wn = wid >> 1;
    int g = lane >> 2, t = lane & 3;

    // A staging (conflict-free): row = tid&127, word half = (tid>>7)*8
    int ar = tid & 127, aw = (tid >> 7) * 8, acf = (tid >> 7) * 16;
    bool aval = (m0 + ar < M);
    const float* arow = x + (size_t)(aval ? g_tok[e * NTOK + m0 + ar] : 0) * DIN + acf;
    // B staging (conflict-free): k-pair row kp = tid>>4, strided n columns
    int kp = tid >> 4, nb4 = (tid & 15) * 4;
    const float* b0p = W1 + (size_t)e * DIN * DH + (size_t)(2 * kp) * DH + nb4;
    const float* b1p = b0p + DH;

    float acc[4][8][4];
#pragma unroll
    for (int i = 0; i < 4; i++)
#pragma unroll
        for (int j = 0; j < 8; j++)
#pragma unroll
            for (int q = 0; q < 4; q++) acc[i][j][q] = 0.f;

    float4 av[4], bv0[4], bv1[4];
#pragma unroll
    for (int q = 0; q < 4; q++)
        av[q] = aval ? *(const float4*)(arow + q * 4) : make_float4(0.f, 0.f, 0.f, 0.f);
#pragma unroll
    for (int q = 0; q < 4; q++) {
        bv0[q] = *(const float4*)(b0p + q * 64);
        bv1[q] = *(const float4*)(b1p + q * 64);
    }

    const int NK = DIN / 32;   // 32 chunks of 32 k
    for (int kc = 0; kc < NK; kc++) {
        // pack + store A (8 words = 2 uint4), banks r*20 mod 32 distinct per phase
        {
            uint4 w0, w1;
            w0.x = pkh2(av[0].x, av[0].y); w0.y = pkh2(av[0].z, av[0].w);
            w0.z = pkh2(av[1].x, av[1].y); w0.w = pkh2(av[1].z, av[1].w);
            w1.x = pkh2(av[2].x, av[2].y); w1.y = pkh2(av[2].z, av[2].w);
            w1.z = pkh2(av[3].x, av[3].y); w1.w = pkh2(av[3].z, av[3].w);
            *(uint4*)&As[ar][aw + 0] = w0;
            *(uint4*)&As[ar][aw + 4] = w1;
        }
        // pack + store B: word(kp, n) = {B[2kp][n], B[2kp+1][n]} at n = nb4 + 64q
#pragma unroll
        for (int q = 0; q < 4; q++) {
            uint4 w;
            w.x = pkh2(bv0[q].x, bv1[q].x);
            w.y = pkh2(bv0[q].y, bv1[q].y);
            w.z = pkh2(bv0[q].z, bv1[q].z);
            w.w = pkh2(bv0[q].w, bv1[q].w);
            *(uint4*)&Bs[kp][nb4 + q * 64] = w;
        }
        __syncthreads();

        if (kc + 1 < NK) {
            int k0 = (kc + 1) * 32;
#pragma unroll
            for (int q = 0; q < 4; q++)
                av[q] = aval ? *(const float4*)(arow + k0 + q * 4)
                             : make_float4(0.f, 0.f, 0.f, 0.f);
            size_t bo = (size_t)k0 * DH;
#pragma unroll
            for (int q = 0; q < 4; q++) {
                bv0[q] = *(const float4*)(b0p + bo + q * 64);
                bv1[q] = *(const float4*)(b1p + bo + q * 64);
            }
        }

#pragma unroll
        for (int kk = 0; kk < 2; kk++) {
            int kb = kk * 8;
            uint32_t af[4][4], bf[8][2];
#pragma unroll
            for (int i = 0; i < 4; i++) {
                int rb = wm * 64 + i * 16;
                af[i][0] = As[rb + g][kb + t];
                af[i][1] = As[rb + g + 8][kb + t];
                af[i][2] = As[rb + g][kb + t + 4];
                af[i][3] = As[rb + g + 8][kb + t + 4];
            }
#pragma unroll
            for (int j = 0; j < 8; j++) {
                int cb = wn * 64 + j * 8;
                bf[j][0] = Bs[kb + t][cb + g];
                bf[j][1] = Bs[kb + t + 4][cb + g];
            }
#pragma unroll
            for (int i = 0; i < 4; i++)
#pragma unroll
                for (int j = 0; j < 8; j++)
                    mma_f16(acc[i][j], af[i], bf[j]);
        }
        __syncthreads();
    }

    // epilogue: relu(acc + bias) -> g_H
#pragma unroll
    for (int i = 0; i < 4; i++) {
        int r0 = m0 + wm * 64 + i * 16 + g;
        int r1 = r0 + 8;
#pragma unroll
        for (int j = 0; j < 8; j++) {
            int col = wn * 64 + j * 8 + 2 * t;
            float bx = b1[(size_t)e * DH + col];
            float by = b1[(size_t)e * DH + col + 1];
            if (r0 < M) {
                float2 h0 = make_float2(fmaxf(acc[i][j][0] + bx, 0.f),
                                        fmaxf(acc[i][j][1] + by, 0.f));
                *(float2*)(g_H + ((size_t)e * NTOK + r0) * DH + col) = h0;
            }
            if (r1 < M) {
                float2 h1 = make_float2(fmaxf(acc[i][j][2] + bx, 0.f),
                                        fmaxf(acc[i][j][3] + by, 0.f));
                *(float2*)(g_H + ((size_t)e * NTOK + r1) * DH + col) = h1;
            }
        }
    }
}

// ---------------- GEMM2: g_Y[slot] = wt*(H @ W2 + b2), K=256, Ncols=1024 ----------
__global__ void __launch_bounds__(256, 1)
moe_gemm2(const float* __restrict__ W2, const float* __restrict__ b2) {
    int e = blockIdx.z, m0 = blockIdx.y * BM, n0 = blockIdx.x * BN;
    int M = g_count[e];
    if (m0 >= M) return;

    __shared__ uint32_t As[BM][ASTR];
    __shared__ uint32_t Bs[BKW][BSTR];

    int tid = threadIdx.x, wid = tid >> 5, lane = tid & 31;
    int wm = wid & 1, wn = wid >> 1;
    int g = lane >> 2, t = lane & 3;

    int ar = tid & 127, aw = (tid >> 7) * 8, acf = (tid >> 7) * 16;
    bool aval = (m0 + ar < M);
    const float* arow = g_H + ((size_t)e * NTOK + (m0 + ar)) * DH + acf;
    int kp = tid >> 4, nb4 = (tid & 15) * 4;
    const float* b0p = W2 + (size_t)e * DH * DOUT + (size_t)(2 * kp) * DOUT + n0 + nb4;
    const float* b1p = b0p + DOUT;

    float acc[4][8][4];
#pragma unroll
    for (int i = 0; i < 4; i++)
#pragma unroll
        for (int j = 0; j < 8; j++)
#pragma unroll
            for (int q = 0; q < 4; q++) acc[i][j][q] = 0.f;

    float4 av[4], bv0[4], bv1[4];
#pragma unroll
    for (int q = 0; q < 4; q++)
        av[q] = aval ? *(const float4*)(arow + q * 4) : make_float4(0.f, 0.f, 0.f, 0.f);
#pragma unroll
    for (int q = 0; q < 4; q++) {
        bv0[q] = *(const float4*)(b0p + q * 64);
        bv1[q] = *(const float4*)(b1p + q * 64);
    }

    const int NK = DH / 32;    // 8 chunks
    for (int kc = 0; kc < NK; kc++) {
        {
            uint4 w0, w1;
            w0.x = pkh2(av[0].x, av[0].y); w0.y = pkh2(av[0].z, av[0].w);
            w0.z = pkh2(av[1].x, av[1].y); w0.w = pkh2(av[1].z, av[1].w);
            w1.x = pkh2(av[2].x, av[2].y); w1.y = pkh2(av[2].z, av[2].w);
            w1.z = pkh2(av[3].x, av[3].y); w1.w = pkh2(av[3].z, av[3].w);
            *(uint4*)&As[ar][aw + 0] = w0;
            *(uint4*)&As[ar][aw + 4] = w1;
        }
#pragma unroll
        for (int q = 0; q < 4; q++) {
            uint4 w;
            w.x = pkh2(bv0[q].x, bv1[q].x);
            w.y = pkh2(bv0[q].y, bv1[q].y);
            w.z = pkh2(bv0[q].z, bv1[q].z);
            w.w = pkh2(bv0[q].w, bv1[q].w);
            *(uint4*)&Bs[kp][nb4 + q * 64] = w;
        }
        __syncthreads();

        if (kc + 1 < NK) {
            int k0 = (kc + 1) * 32;
#pragma unroll
            for (int q = 0; q < 4; q++)
                av[q] = aval ? *(const float4*)(arow + k0 + q * 4)
                             : make_float4(0.f, 0.f, 0.f, 0.f);
            size_t bo = (size_t)k0 * DOUT;
#pragma unroll
            for (int q = 0; q < 4; q++) {
                bv0[q] = *(const float4*)(b0p + bo + q * 64);
                bv1[q] = *(const float4*)(b1p + bo + q * 64);
            }
        }

#pragma unroll
        for (int kk = 0; kk < 2; kk++) {
            int kb = kk * 8;
            uint32_t af[4][4], bf[8][2];
#pragma unroll
            for (int i = 0; i < 4; i++) {
                int rb = wm * 64 + i * 16;
                af[i][0] = As[rb + g][kb + t];
                af[i][1] = As[rb + g + 8][kb + t];
                af[i][2] = As[rb + g][kb + t + 4];
                af[i][3] = As[rb + g + 8][kb + t + 4];
            }
#pragma unroll
            for (int j = 0; j < 8; j++) {
                int cb = wn * 64 + j * 8;
                bf[j][0] = Bs[kb + t][cb + g];
                bf[j][1] = Bs[kb + t + 4][cb + g];
            }
#pragma unroll
            for (int i = 0; i < 4; i++)
#pragma unroll
                for (int j = 0; j < 8; j++)
                    mma_f16(acc[i][j], af[i], bf[j]);
        }
        __syncthreads();
    }

    // epilogue: g_Y[slot] = wt * (acc + bias)
#pragma unroll
    for (int i = 0; i < 4; i++) {
        int r0 = m0 + wm * 64 + i * 16 + g;
        int r1 = r0 + 8;
        float w0 = (r0 < M) ? g_wt[e * NTOK + r0] : 0.f;
        float w1 = (r1 < M) ? g_wt[e * NTOK + r1] : 0.f;
#pragma unroll
        for (int j = 0; j < 8; j++) {
            int col = n0 + wn * 64 + j * 8 + 2 * t;
            float bx = b2[(size_t)e * DOUT + col];
            float by = b2[(size_t)e * DOUT + col + 1];
            if (r0 < M) {
                float2 v = make_float2(w0 * (acc[i][j][0] + bx), w0 * (acc[i][j][1] + by));
                *(float2*)(g_Y + ((size_t)e * NTOK + r0) * DOUT + col) = v;
            }
            if (r1 < M) {
                float2 v = make_float2(w1 * (acc[i][j][2] + bx), w1 * (acc[i][j][3] + by));
                *(float2*)(g_Y + ((size_t)e * NTOK + r1) * DOUT + col) = v;
            }
        }
    }
}

// ---------------- combine: out[tok] = Y[slotA] + Y[slotB] ----------------
__global__ void combine_kernel(float* __restrict__ out) {
    int tok = blockIdx.x, tid = threadIdx.x;
    int sa = g_slot2[2 * tok], sb = g_slot2[2 * tok + 1];
    float4 a = ((const float4*)(g_Y + (size_t)sa * DOUT))[tid];
    float4 b = ((const float4*)(g_Y + (size_t)sb * DOUT))[tid];
    ((float4*)(out + (size_t)tok * DOUT))[tid] =
        make_float4(a.x + b.x, a.y + b.y, a.z + b.z, a.w + b.w);
}

// ---------------- launch ----------------
extern "C" void kernel_launch(void* const* d_in, const int* in_sizes, int n_in,
                              void* d_out, int out_size) {
    const float* x  = (const float*)d_in[0];
    const float* Wg = (const float*)d_in[1];
    const float* bg = (const float*)d_in[2];
    const float* W1 = (const float*)d_in[3];
    const float* b1 = (const float*)d_in[4];
    const float* W2 = (const float*)d_in[5];
    const float* b2 = (const float*)d_in[6];

    int N = in_sizes[0] / DIN;   // 16384
    float* out      = (float*)d_out;
    float* gate_out = (float*)d_out + (size_t)N * DOUT;

    zcnt_kernel<<<1, 32>>>();
    moe_gate_kernel<<<(N * 32 + 255) / 256, 256>>>(x, Wg, bg, gate_out, N);

    dim3 g1(1, NTOK / BM, NEXP);          // 1 x 128 x 8
    moe_gemm1<<<g1, 256>>>(x, W1, b1);

    dim3 g2(DOUT / BN, NTOK / BM, NEXP);  // 4 x 128 x 8
    moe_gemm2<<<g2, 256>>>(W2, b2);

    combine_kernel<<<N, 256>>>(out);
}